// round 12
// baseline (speedup 1.0000x reference)
#include <cuda_runtime.h>
#include <cstdint>

// Problem constants
#define Bb 2
#define Nn 100000
#define Ff 64
#define Ee 800000
#define EO 16
#define NO 64

// Scratch (device globals — no allocation allowed)
__device__ float g_P[Bb * Nn * 32];    // [b][n][0:16]=x·W1, [16:32]=x·W2
__device__ float g_agg[Bb * Nn * 16];  // aggregation buffer

// ---------------------------------------------------------------------------
// Packed fp32x2 helpers (Blackwell sm_100+)
// ---------------------------------------------------------------------------
__device__ __forceinline__ unsigned long long pack2(float a, float b) {
    unsigned long long r;
    asm("mov.b64 %0, {%1, %2};" : "=l"(r) : "f"(a), "f"(b));
    return r;
}
__device__ __forceinline__ float2 unpack2(unsigned long long v) {
    float2 r;
    asm("mov.b64 {%0, %1}, %2;" : "=f"(r.x), "=f"(r.y) : "l"(v));
    return r;
}
__device__ __forceinline__ unsigned long long fma2(unsigned long long a,
                                                   unsigned long long b,
                                                   unsigned long long c) {
    unsigned long long d;
    asm("fma.rn.f32x2 %0, %1, %2, %3;" : "=l"(d) : "l"(a), "l"(b), "l"(c));
    return d;
}

// ---------------------------------------------------------------------------
// MUFU sigmoid: 2 MUFU + 2 FMA-pipe ops; MUFU pipe otherwise idle.
// ---------------------------------------------------------------------------
__device__ __forceinline__ float sigmoid_mufu(float x) {
    float e, r;
    asm("ex2.approx.ftz.f32 %0, %1;" : "=f"(e) : "f"(x * -1.4426950408889634f));
    asm("rcp.approx.ftz.f32 %0, %1;" : "=f"(r) : "f"(1.0f + e));
    return r;
}

// ---------------------------------------------------------------------------
// K0: zero g_agg. Split out of k1 so the launch sequence is 5 long and the
// profiler's fixed capture slot (launch #4) lands on k2_edges(batch 1).
// ---------------------------------------------------------------------------
__global__ __launch_bounds__(256) void k_zero() {
    const int tid = blockIdx.x * blockDim.x + threadIdx.x;
    const int nth = gridDim.x * blockDim.x;
    const float4 z4 = make_float4(0.f, 0.f, 0.f, 0.f);
    for (int i = tid; i < (Bb * Nn * 16) / 4; i += nth)
        ((float4*)g_agg)[i] = z4;
}

// ---------------------------------------------------------------------------
// K1 (exact round-7 form, 35.8us proven, minus the zeroing loop):
// P = x @ [W1|W2]. Round-4 lane mapping + 2-deep LDG prefetch; warp covers
// 2 nodes/iter with 4 independent fma2 chains; double-buffered smem.
// ---------------------------------------------------------------------------
__global__ __launch_bounds__(128) void k1_precompute(
    const float* __restrict__ x, const float* __restrict__ W_e) {
    __shared__ float xs[4][2][128];   // [warp][buf][2 node rows]

    const int tid = blockIdx.x * blockDim.x + threadIdx.x;
    const int nth = gridDim.x * blockDim.x;

    const int lane  = threadIdx.x & 31;
    const int winb  = threadIdx.x >> 5;
    const int col   = lane & 15;
    const int rbase = (lane >= 16) ? 64 : 0;    // lanes 16..31 -> W2 rows

    unsigned long long w2[32];
#pragma unroll
    for (int k = 0; k < 32; k++)
        w2[k] = pack2(__ldg(W_e + (rbase + 2 * k) * EO + col),
                      __ldg(W_e + (rbase + 2 * k + 1) * EO + col));

    const uint32_t sb0 = (uint32_t)__cvta_generic_to_shared(&xs[winb][0][0]);
    const uint32_t sb1 = (uint32_t)__cvta_generic_to_shared(&xs[winb][1][0]);

    const int NP     = (Bb * Nn) / 2;
    const int warpId = tid >> 5;
    const int nwarps = nth >> 5;

    // 2-deep prefetch pipeline (tail prefetches clamp; values never used).
    float4 xv0 = ((const float4*)(x + (size_t)warpId * 128))[lane];
    {
        const int pr1 = warpId + nwarps;
        const int c1  = pr1 < NP ? pr1 : NP - 1;
        float4 xv1 = ((const float4*)(x + (size_t)c1 * 128))[lane];

        int p = 0;
        for (int pair = warpId; pair < NP; pair += nwarps) {
            ((float4*)(p ? xs[winb][1] : xs[winb][0]))[lane] = xv0;
            __syncwarp();
            xv0 = xv1;
            const int pr2 = pair + 2 * nwarps;
            const int c2  = pr2 < NP ? pr2 : NP - 1;
            xv1 = ((const float4*)(x + (size_t)c2 * 128))[lane];  // 2 ahead

            const uint32_t sb = p ? sb1 : sb0;
            unsigned long long accA0 = 0ull, accB0 = 0ull;
            unsigned long long accA1 = 0ull, accB1 = 0ull;
#pragma unroll
            for (int kk = 0; kk < 16; kk++) {
                unsigned long long a0, a1, b0, b1;
                asm volatile("ld.shared.v2.b64 {%0, %1}, [%2];"
                             : "=l"(a0), "=l"(a1) : "r"(sb + kk * 16));
                asm volatile("ld.shared.v2.b64 {%0, %1}, [%2];"
                             : "=l"(b0), "=l"(b1) : "r"(sb + 256 + kk * 16));
                accA0 = fma2(a0, w2[2 * kk],     accA0);
                accB0 = fma2(a1, w2[2 * kk + 1], accB0);
                accA1 = fma2(b0, w2[2 * kk],     accA1);
                accB1 = fma2(b1, w2[2 * kk + 1], accB1);
            }

            const float2 sA0 = unpack2(accA0), sB0 = unpack2(accB0);
            const float2 sA1 = unpack2(accA1), sB1 = unpack2(accB1);
            g_P[(size_t)pair * 64 + lane]      = (sA0.x + sA0.y) + (sB0.x + sB0.y);
            g_P[(size_t)pair * 64 + 32 + lane] = (sA1.x + sA1.y) + (sB1.x + sB1.y);
            p ^= 1;
        }
    }
}

// ---------------------------------------------------------------------------
// K2 (round-7 semantics, one batch per launch): 4 threads/edge + 1-deep
// software prefetch of next indices + P gathers before current REDs.
// Launched twice (b=0, b=1) so the profiler's slot-#4 capture shows K2.
// ---------------------------------------------------------------------------
__global__ __launch_bounds__(256) void k2_edges(
    const int* __restrict__ esrc, const int* __restrict__ etgt,
    const float* __restrict__ ew, const float* __restrict__ W_e,
    const float* __restrict__ b_e, int b) {
    const int tid0 = blockIdx.x * blockDim.x + threadIdx.x;
    const int nth  = gridDim.x * blockDim.x;   // multiple of 4 -> q invariant
    const int q    = tid0 & 3;

    const float4 w3 = ((const float4*)(W_e + 128 * EO))[q];  // ew row
    const float4 bq = ((const float4*)b_e)[q];

    const float* Pb = g_P + (size_t)b * Nn * 32;
    float* aggb     = g_agg + (size_t)b * Nn * 16;

    // Prologue: stage iteration 0.
    int   e  = tid0 >> 2;
    int   s  = __ldg(esrc + e);
    int   t  = __ldg(etgt + e);
    float wv = __ldg(ew + e);
    float4 p1 = __ldg((const float4*)(Pb + (size_t)s * 32 + q * 4));
    float4 p2 = __ldg((const float4*)(Pb + (size_t)t * 32 + 16 + q * 4));

    for (int gid = tid0; gid < Ee * 4; gid += nth) {
        // Prefetch next iteration (clamped at the tail; values unused).
        const int gidn = gid + nth;
        const int en   = (gidn < Ee * 4) ? (gidn >> 2) : e;
        const int   sn  = __ldg(esrc + en);
        const int   tn  = __ldg(etgt + en);
        const float wvn = __ldg(ew + en);
        const float4 p1n = __ldg((const float4*)(Pb + (size_t)sn * 32 + q * 4));
        const float4 p2n = __ldg((const float4*)(Pb + (size_t)tn * 32 + 16 + q * 4));

        float4 h;
        h.x = sigmoid_mufu(fmaf(wv, w3.x, p1.x + p2.x + bq.x));
        h.y = sigmoid_mufu(fmaf(wv, w3.y, p1.y + p2.y + bq.y));
        h.z = sigmoid_mufu(fmaf(wv, w3.z, p1.z + p2.z + bq.z));
        h.w = sigmoid_mufu(fmaf(wv, w3.w, p1.w + p2.w + bq.w));

        float* ta = aggb + (size_t)t * 16 + q * 4;
        float* sa = aggb + (size_t)s * 16 + q * 4;
        asm volatile("red.global.add.v4.f32 [%0], {%1,%2,%3,%4};"
                     :: "l"(ta), "f"(h.x), "f"(h.y), "f"(h.z), "f"(h.w) : "memory");
        asm volatile("red.global.add.v4.f32 [%0], {%1,%2,%3,%4};"
                     :: "l"(sa), "f"(-h.x), "f"(-h.y), "f"(-h.z), "f"(-h.w) : "memory");

        e = en; s = sn; t = tn; wv = wvn; p1 = p1n; p2 = p2n;
    }
}

// ---------------------------------------------------------------------------
// K3: out[b,n,:] = sigmoid(agg[b,n,:16] @ W_n[16,64] + b_n). Unchanged.
// ---------------------------------------------------------------------------
__global__ __launch_bounds__(256) void k3_nodes(
    const float* __restrict__ W_n, const float* __restrict__ b_n,
    float* __restrict__ out) {
    const int lane = threadIdx.x & 31;

    unsigned long long wA2[8], wB2[8];
#pragma unroll
    for (int j = 0; j < 8; j++) {
        wA2[j] = pack2(__ldg(W_n + (2 * j) * NO + lane),
                       __ldg(W_n + (2 * j + 1) * NO + lane));
        wB2[j] = pack2(__ldg(W_n + (2 * j) * NO + lane + 32),
                       __ldg(W_n + (2 * j + 1) * NO + lane + 32));
    }
    const float bA = __ldg(b_n + lane);
    const float bB = __ldg(b_n + lane + 32);

    const int tid    = blockIdx.x * blockDim.x + threadIdx.x;
    const int warpId = tid >> 5;
    const int nwarps = (gridDim.x * blockDim.x) >> 5;

    for (int node = warpId; node < Bb * Nn; node += nwarps) {
        const float* ag = g_agg + (size_t)node * 16;
        unsigned long long a[8];
#pragma unroll
        for (int j = 0; j < 4; j++)
            asm volatile("ld.global.nc.v2.b64 {%0, %1}, [%2];"
                         : "=l"(a[2 * j]), "=l"(a[2 * j + 1])
                         : "l"(ag + 4 * j));

        unsigned long long accA = 0ull, accB = 0ull;
#pragma unroll
        for (int j = 0; j < 8; j++) {
            accA = fma2(a[j], wA2[j], accA);
            accB = fma2(a[j], wB2[j], accB);
        }
        float2 sA = unpack2(accA), sB = unpack2(accB);
        out[(size_t)node * NO + lane]      = sigmoid_mufu(bA + sA.x + sA.y);
        out[(size_t)node * NO + lane + 32] = sigmoid_mufu(bB + sB.x + sB.y);
    }
}

// ---------------------------------------------------------------------------
extern "C" void kernel_launch(void* const* d_in, const int* in_sizes, int n_in,
                              void* d_out, int out_size) {
    const float* x    = (const float*)d_in[0];
    const int*   esrc = (const int*)d_in[1];
    const int*   etgt = (const int*)d_in[2];
    const float* ew   = (const float*)d_in[3];
    const float* W_e  = (const float*)d_in[4];
    const float* b_e  = (const float*)d_in[5];
    const float* W_n  = (const float*)d_in[6];
    const float* b_n  = (const float*)d_in[7];
    float* out = (float*)d_out;

    k_zero<<<148 * 4, 256>>>();                               // launch 1
    k1_precompute<<<148 * 16, 128>>>(x, W_e);                 // launch 2
    k2_edges<<<148 * 8, 256>>>(esrc, etgt, ew, W_e, b_e, 0);  // launch 3
    k2_edges<<<148 * 8, 256>>>(esrc, etgt, ew, W_e, b_e, 1);  // launch 4 <- profiled
    k3_nodes<<<148 * 8, 256>>>(W_n, b_n, out);                // launch 5
}

// round 14
// speedup vs baseline: 1.0153x; 1.0153x over previous
#include <cuda_runtime.h>
#include <cstdint>

// Problem constants
#define Bb 2
#define Nn 100000
#define Ff 64
#define Ee 800000
#define EO 16
#define NO 64

// Scratch (device globals — no allocation allowed)
__device__ float g_P[Bb * Nn * 32];    // [b][n][0:16]=x·W1, [16:32]=x·W2
__device__ float g_agg[Bb * Nn * 16];  // aggregation buffer

// ---------------------------------------------------------------------------
// Packed fp32x2 helpers (Blackwell sm_100+)
// ---------------------------------------------------------------------------
__device__ __forceinline__ unsigned long long pack2(float a, float b) {
    unsigned long long r;
    asm("mov.b64 %0, {%1, %2};" : "=l"(r) : "f"(a), "f"(b));
    return r;
}
__device__ __forceinline__ float2 unpack2(unsigned long long v) {
    float2 r;
    asm("mov.b64 {%0, %1}, %2;" : "=f"(r.x), "=f"(r.y) : "l"(v));
    return r;
}
__device__ __forceinline__ unsigned long long fma2(unsigned long long a,
                                                   unsigned long long b,
                                                   unsigned long long c) {
    unsigned long long d;
    asm("fma.rn.f32x2 %0, %1, %2, %3;" : "=l"(d) : "l"(a), "l"(b), "l"(c));
    return d;
}

// ---------------------------------------------------------------------------
// MUFU sigmoid: 2 MUFU + 2 FMA-pipe ops; MUFU pipe otherwise idle.
// ---------------------------------------------------------------------------
__device__ __forceinline__ float sigmoid_mufu(float x) {
    float e, r;
    asm("ex2.approx.ftz.f32 %0, %1;" : "=f"(e) : "f"(x * -1.4426950408889634f));
    asm("rcp.approx.ftz.f32 %0, %1;" : "=f"(r) : "f"(1.0f + e));
    return r;
}

// ---------------------------------------------------------------------------
// K1 (exact round-7 form, 35.8us proven): zero g_agg, then P = x @ [W1|W2].
// Round-4 lane mapping + 2-deep LDG prefetch; warp covers 2 nodes/iter with
// 4 independent fma2 chains; double-buffered smem.
// ---------------------------------------------------------------------------
__global__ __launch_bounds__(128) void k1_precompute(
    const float* __restrict__ x, const float* __restrict__ W_e) {
    __shared__ float xs[4][2][128];   // [warp][buf][2 node rows]

    const int tid = blockIdx.x * blockDim.x + threadIdx.x;
    const int nth = gridDim.x * blockDim.x;

    // Zero the aggregation buffer (vectorized)
    const float4 z4 = make_float4(0.f, 0.f, 0.f, 0.f);
    for (int i = tid; i < (Bb * Nn * 16) / 4; i += nth)
        ((float4*)g_agg)[i] = z4;

    const int lane  = threadIdx.x & 31;
    const int winb  = threadIdx.x >> 5;
    const int col   = lane & 15;
    const int rbase = (lane >= 16) ? 64 : 0;    // lanes 16..31 -> W2 rows

    unsigned long long w2[32];
#pragma unroll
    for (int k = 0; k < 32; k++)
        w2[k] = pack2(__ldg(W_e + (rbase + 2 * k) * EO + col),
                      __ldg(W_e + (rbase + 2 * k + 1) * EO + col));

    const uint32_t sb0 = (uint32_t)__cvta_generic_to_shared(&xs[winb][0][0]);
    const uint32_t sb1 = (uint32_t)__cvta_generic_to_shared(&xs[winb][1][0]);

    const int NP     = (Bb * Nn) / 2;
    const int warpId = tid >> 5;
    const int nwarps = nth >> 5;

    // 2-deep prefetch pipeline (tail prefetches clamp; values never used).
    float4 xv0 = ((const float4*)(x + (size_t)warpId * 128))[lane];
    {
        const int pr1 = warpId + nwarps;
        const int c1  = pr1 < NP ? pr1 : NP - 1;
        float4 xv1 = ((const float4*)(x + (size_t)c1 * 128))[lane];

        int p = 0;
        for (int pair = warpId; pair < NP; pair += nwarps) {
            ((float4*)(p ? xs[winb][1] : xs[winb][0]))[lane] = xv0;
            __syncwarp();
            xv0 = xv1;
            const int pr2 = pair + 2 * nwarps;
            const int c2  = pr2 < NP ? pr2 : NP - 1;
            xv1 = ((const float4*)(x + (size_t)c2 * 128))[lane];  // 2 ahead

            const uint32_t sb = p ? sb1 : sb0;
            unsigned long long accA0 = 0ull, accB0 = 0ull;
            unsigned long long accA1 = 0ull, accB1 = 0ull;
#pragma unroll
            for (int kk = 0; kk < 16; kk++) {
                unsigned long long a0, a1, b0, b1;
                asm volatile("ld.shared.v2.b64 {%0, %1}, [%2];"
                             : "=l"(a0), "=l"(a1) : "r"(sb + kk * 16));
                asm volatile("ld.shared.v2.b64 {%0, %1}, [%2];"
                             : "=l"(b0), "=l"(b1) : "r"(sb + 256 + kk * 16));
                accA0 = fma2(a0, w2[2 * kk],     accA0);
                accB0 = fma2(a1, w2[2 * kk + 1], accB0);
                accA1 = fma2(b0, w2[2 * kk],     accA1);
                accB1 = fma2(b1, w2[2 * kk + 1], accB1);
            }

            const float2 sA0 = unpack2(accA0), sB0 = unpack2(accB0);
            const float2 sA1 = unpack2(accA1), sB1 = unpack2(accB1);
            g_P[(size_t)pair * 64 + lane]      = (sA0.x + sA0.y) + (sB0.x + sB0.y);
            g_P[(size_t)pair * 64 + 32 + lane] = (sA1.x + sA1.y) + (sB1.x + sB1.y);
            p ^= 1;
        }
    }
}

// ---------------------------------------------------------------------------
// K2 (exact round-7 form — at the REDG lane-rate floor, ~31us/batch):
// 4 threads/edge-instance + 1-deep software prefetch of next indices +
// P gathers before current REDs. Internal batch loop (single launch).
// ---------------------------------------------------------------------------
__global__ __launch_bounds__(256) void k2_edges(
    const int* __restrict__ esrc, const int* __restrict__ etgt,
    const float* __restrict__ ew, const float* __restrict__ W_e,
    const float* __restrict__ b_e) {
    const int tid0 = blockIdx.x * blockDim.x + threadIdx.x;
    const int nth  = gridDim.x * blockDim.x;   // multiple of 4 -> q invariant
    const int q    = tid0 & 3;

    const float4 w3 = ((const float4*)(W_e + 128 * EO))[q];  // ew row
    const float4 bq = ((const float4*)b_e)[q];

#pragma unroll 1
    for (int b = 0; b < Bb; b++) {
        const float* Pb = g_P + (size_t)b * Nn * 32;
        float* aggb     = g_agg + (size_t)b * Nn * 16;

        // Prologue: stage iteration 0.
        int   e  = tid0 >> 2;
        int   s  = __ldg(esrc + e);
        int   t  = __ldg(etgt + e);
        float wv = __ldg(ew + e);
        float4 p1 = __ldg((const float4*)(Pb + (size_t)s * 32 + q * 4));
        float4 p2 = __ldg((const float4*)(Pb + (size_t)t * 32 + 16 + q * 4));

        for (int gid = tid0; gid < Ee * 4; gid += nth) {
            // Prefetch next iteration (clamped at the tail; values unused).
            const int gidn = gid + nth;
            const int en   = (gidn < Ee * 4) ? (gidn >> 2) : e;
            const int   sn  = __ldg(esrc + en);
            const int   tn  = __ldg(etgt + en);
            const float wvn = __ldg(ew + en);
            const float4 p1n = __ldg((const float4*)(Pb + (size_t)sn * 32 + q * 4));
            const float4 p2n = __ldg((const float4*)(Pb + (size_t)tn * 32 + 16 + q * 4));

            float4 h;
            h.x = sigmoid_mufu(fmaf(wv, w3.x, p1.x + p2.x + bq.x));
            h.y = sigmoid_mufu(fmaf(wv, w3.y, p1.y + p2.y + bq.y));
            h.z = sigmoid_mufu(fmaf(wv, w3.z, p1.z + p2.z + bq.z));
            h.w = sigmoid_mufu(fmaf(wv, w3.w, p1.w + p2.w + bq.w));

            float* ta = aggb + (size_t)t * 16 + q * 4;
            float* sa = aggb + (size_t)s * 16 + q * 4;
            asm volatile("red.global.add.v4.f32 [%0], {%1,%2,%3,%4};"
                         :: "l"(ta), "f"(h.x), "f"(h.y), "f"(h.z), "f"(h.w) : "memory");
            asm volatile("red.global.add.v4.f32 [%0], {%1,%2,%3,%4};"
                         :: "l"(sa), "f"(-h.x), "f"(-h.y), "f"(-h.z), "f"(-h.w) : "memory");

            e = en; s = sn; t = tn; wv = wvn; p1 = p1n; p2 = p2n;
        }
    }
}

// ---------------------------------------------------------------------------
// K3: out[b,n,:] = sigmoid(agg[b,n,:16] @ W_n[16,64] + b_n). Warp per node.
// Lane owns ADJACENT cols {2l, 2l+1} -> single STG.64 (float2) per node-half
// instead of two strided STG.32, still fully coalesced 256B per warp store.
// ---------------------------------------------------------------------------
__global__ __launch_bounds__(256) void k3_nodes(
    const float* __restrict__ W_n, const float* __restrict__ b_n,
    float* __restrict__ out) {
    const int lane = threadIdx.x & 31;
    const int c0   = 2 * lane;       // owned columns c0, c0+1

    // wA2[j] = {W_n[2j][c0], W_n[2j+1][c0]}, wB2[j] same for col c0+1
    unsigned long long wA2[8], wB2[8];
#pragma unroll
    for (int j = 0; j < 8; j++) {
        wA2[j] = pack2(__ldg(W_n + (2 * j) * NO + c0),
                       __ldg(W_n + (2 * j + 1) * NO + c0));
        wB2[j] = pack2(__ldg(W_n + (2 * j) * NO + c0 + 1),
                       __ldg(W_n + (2 * j + 1) * NO + c0 + 1));
    }
    const float bA = __ldg(b_n + c0);
    const float bB = __ldg(b_n + c0 + 1);

    const int tid    = blockIdx.x * blockDim.x + threadIdx.x;
    const int warpId = tid >> 5;
    const int nwarps = (gridDim.x * blockDim.x) >> 5;

    for (int node = warpId; node < Bb * Nn; node += nwarps) {
        const float* ag = g_agg + (size_t)node * 16;
        unsigned long long a[8];
#pragma unroll
        for (int j = 0; j < 4; j++)
            asm volatile("ld.global.nc.v2.b64 {%0, %1}, [%2];"
                         : "=l"(a[2 * j]), "=l"(a[2 * j + 1])
                         : "l"(ag + 4 * j));

        unsigned long long accA = 0ull, accB = 0ull;
#pragma unroll
        for (int j = 0; j < 8; j++) {
            accA = fma2(a[j], wA2[j], accA);
            accB = fma2(a[j], wB2[j], accB);
        }
        float2 sA = unpack2(accA), sB = unpack2(accB);
        float2 o;
        o.x = sigmoid_mufu(bA + sA.x + sA.y);
        o.y = sigmoid_mufu(bB + sB.x + sB.y);
        *(float2*)(out + (size_t)node * NO + c0) = o;   // one STG.64
    }
}

// ---------------------------------------------------------------------------
extern "C" void kernel_launch(void* const* d_in, const int* in_sizes, int n_in,
                              void* d_out, int out_size) {
    const float* x    = (const float*)d_in[0];
    const int*   esrc = (const int*)d_in[1];
    const int*   etgt = (const int*)d_in[2];
    const float* ew   = (const float*)d_in[3];
    const float* W_e  = (const float*)d_in[4];
    const float* b_e  = (const float*)d_in[5];
    const float* W_n  = (const float*)d_in[6];
    const float* b_n  = (const float*)d_in[7];
    float* out = (float*)d_out;

    k1_precompute<<<148 * 16, 128>>>(x, W_e);
    k2_edges<<<148 * 8, 256>>>(esrc, etgt, ew, W_e, b_e);
    k3_nodes<<<148 * 8, 256>>>(W_n, b_n, out);
}

// round 15
// speedup vs baseline: 1.0344x; 1.0188x over previous
#include <cuda_runtime.h>
#include <cstdint>

// Problem constants
#define Bb 2
#define Nn 100000
#define Ff 64
#define Ee 800000
#define EO 16
#define NO 64

// Scratch (device globals — no allocation allowed)
__device__ float g_P[Bb * Nn * 32];    // [b][n][0:16]=x·W1, [16:32]=x·W2
__device__ float g_agg[Bb * Nn * 16];  // aggregation buffer

// ---------------------------------------------------------------------------
// Packed fp32x2 helpers (Blackwell sm_100+)
// ---------------------------------------------------------------------------
__device__ __forceinline__ unsigned long long pack2(float a, float b) {
    unsigned long long r;
    asm("mov.b64 %0, {%1, %2};" : "=l"(r) : "f"(a), "f"(b));
    return r;
}
__device__ __forceinline__ float2 unpack2(unsigned long long v) {
    float2 r;
    asm("mov.b64 {%0, %1}, %2;" : "=f"(r.x), "=f"(r.y) : "l"(v));
    return r;
}
__device__ __forceinline__ unsigned long long fma2(unsigned long long a,
                                                   unsigned long long b,
                                                   unsigned long long c) {
    unsigned long long d;
    asm("fma.rn.f32x2 %0, %1, %2, %3;" : "=l"(d) : "l"(a), "l"(b), "l"(c));
    return d;
}

// ---------------------------------------------------------------------------
// MUFU sigmoid: 2 MUFU + 2 FMA-pipe ops; MUFU pipe otherwise idle.
// ---------------------------------------------------------------------------
__device__ __forceinline__ float sigmoid_mufu(float x) {
    float e, r;
    asm("ex2.approx.ftz.f32 %0, %1;" : "=f"(e) : "f"(x * -1.4426950408889634f));
    asm("rcp.approx.ftz.f32 %0, %1;" : "=f"(r) : "f"(1.0f + e));
    return r;
}

// ---------------------------------------------------------------------------
// K1 half (round-7 body, split by batch): P = x @ [W1|W2] for pair range
// [half*NP2, (half+1)*NP2). half==0 also zeroes ALL of g_agg. Round-4 lane
// mapping + 2-deep LDG prefetch; double-buffered smem.
// ---------------------------------------------------------------------------
__global__ __launch_bounds__(128) void k1_half(
    const float* __restrict__ x, const float* __restrict__ W_e, int half) {
    __shared__ float xs[4][2][128];   // [warp][buf][2 node rows]

    const int tid = blockIdx.x * blockDim.x + threadIdx.x;
    const int nth = gridDim.x * blockDim.x;

    if (half == 0) {   // zero the aggregation buffer (both batches)
        const float4 z4 = make_float4(0.f, 0.f, 0.f, 0.f);
        for (int i = tid; i < (Bb * Nn * 16) / 4; i += nth)
            ((float4*)g_agg)[i] = z4;
    }

    const int lane  = threadIdx.x & 31;
    const int winb  = threadIdx.x >> 5;
    const int col   = lane & 15;
    const int rbase = (lane >= 16) ? 64 : 0;    // lanes 16..31 -> W2 rows

    unsigned long long w2[32];
#pragma unroll
    for (int k = 0; k < 32; k++)
        w2[k] = pack2(__ldg(W_e + (rbase + 2 * k) * EO + col),
                      __ldg(W_e + (rbase + 2 * k + 1) * EO + col));

    const uint32_t sb0 = (uint32_t)__cvta_generic_to_shared(&xs[winb][0][0]);
    const uint32_t sb1 = (uint32_t)__cvta_generic_to_shared(&xs[winb][1][0]);

    const int NP2    = Nn / 2;              // pairs per batch (50000)
    const int base   = half * NP2;
    const int pend   = base + NP2;
    const int warpId = tid >> 5;
    const int nwarps = nth >> 5;

    // 2-deep prefetch pipeline (tail prefetches clamp; values never used).
    const int s0i = base + warpId < pend ? base + warpId : pend - 1;
    float4 xv0 = ((const float4*)(x + (size_t)s0i * 128))[lane];
    {
        const int pr1 = base + warpId + nwarps;
        const int c1  = pr1 < pend ? pr1 : pend - 1;
        float4 xv1 = ((const float4*)(x + (size_t)c1 * 128))[lane];

        int p = 0;
        for (int pair = base + warpId; pair < pend; pair += nwarps) {
            ((float4*)(p ? xs[winb][1] : xs[winb][0]))[lane] = xv0;
            __syncwarp();
            xv0 = xv1;
            const int pr2 = pair + 2 * nwarps;
            const int c2  = pr2 < pend ? pr2 : pend - 1;
            xv1 = ((const float4*)(x + (size_t)c2 * 128))[lane];  // 2 ahead

            const uint32_t sb = p ? sb1 : sb0;
            unsigned long long accA0 = 0ull, accB0 = 0ull;
            unsigned long long accA1 = 0ull, accB1 = 0ull;
#pragma unroll
            for (int kk = 0; kk < 16; kk++) {
                unsigned long long a0, a1, b0, b1;
                asm volatile("ld.shared.v2.b64 {%0, %1}, [%2];"
                             : "=l"(a0), "=l"(a1) : "r"(sb + kk * 16));
                asm volatile("ld.shared.v2.b64 {%0, %1}, [%2];"
                             : "=l"(b0), "=l"(b1) : "r"(sb + 256 + kk * 16));
                accA0 = fma2(a0, w2[2 * kk],     accA0);
                accB0 = fma2(a1, w2[2 * kk + 1], accB0);
                accA1 = fma2(b0, w2[2 * kk],     accA1);
                accB1 = fma2(b1, w2[2 * kk + 1], accB1);
            }

            const float2 sA0 = unpack2(accA0), sB0 = unpack2(accB0);
            const float2 sA1 = unpack2(accA1), sB1 = unpack2(accB1);
            g_P[(size_t)pair * 64 + lane]      = (sA0.x + sA0.y) + (sB0.x + sB0.y);
            g_P[(size_t)pair * 64 + 32 + lane] = (sA1.x + sA1.y) + (sB1.x + sB1.y);
            p ^= 1;
        }
    }
}

// ---------------------------------------------------------------------------
// K2 (round-7 body, one batch per launch): 4 threads/edge + 1-deep software
// prefetch of next indices + P gathers before current REDs. At the REDG
// lane-commit floor (~31us/batch) — overlapped with k1(b1) via streams.
// ---------------------------------------------------------------------------
__global__ __launch_bounds__(256) void k2_edges(
    const int* __restrict__ esrc, const int* __restrict__ etgt,
    const float* __restrict__ ew, const float* __restrict__ W_e,
    const float* __restrict__ b_e, int b) {
    const int tid0 = blockIdx.x * blockDim.x + threadIdx.x;
    const int nth  = gridDim.x * blockDim.x;   // multiple of 4 -> q invariant
    const int q    = tid0 & 3;

    const float4 w3 = ((const float4*)(W_e + 128 * EO))[q];  // ew row
    const float4 bq = ((const float4*)b_e)[q];

    const float* Pb = g_P + (size_t)b * Nn * 32;
    float* aggb     = g_agg + (size_t)b * Nn * 16;

    // Prologue: stage iteration 0.
    int   e  = tid0 >> 2;
    int   s  = __ldg(esrc + e);
    int   t  = __ldg(etgt + e);
    float wv = __ldg(ew + e);
    float4 p1 = __ldg((const float4*)(Pb + (size_t)s * 32 + q * 4));
    float4 p2 = __ldg((const float4*)(Pb + (size_t)t * 32 + 16 + q * 4));

    for (int gid = tid0; gid < Ee * 4; gid += nth) {
        // Prefetch next iteration (clamped at the tail; values unused).
        const int gidn = gid + nth;
        const int en   = (gidn < Ee * 4) ? (gidn >> 2) : e;
        const int   sn  = __ldg(esrc + en);
        const int   tn  = __ldg(etgt + en);
        const float wvn = __ldg(ew + en);
        const float4 p1n = __ldg((const float4*)(Pb + (size_t)sn * 32 + q * 4));
        const float4 p2n = __ldg((const float4*)(Pb + (size_t)tn * 32 + 16 + q * 4));

        float4 h;
        h.x = sigmoid_mufu(fmaf(wv, w3.x, p1.x + p2.x + bq.x));
        h.y = sigmoid_mufu(fmaf(wv, w3.y, p1.y + p2.y + bq.y));
        h.z = sigmoid_mufu(fmaf(wv, w3.z, p1.z + p2.z + bq.z));
        h.w = sigmoid_mufu(fmaf(wv, w3.w, p1.w + p2.w + bq.w));

        float* ta = aggb + (size_t)t * 16 + q * 4;
        float* sa = aggb + (size_t)s * 16 + q * 4;
        asm volatile("red.global.add.v4.f32 [%0], {%1,%2,%3,%4};"
                     :: "l"(ta), "f"(h.x), "f"(h.y), "f"(h.z), "f"(h.w) : "memory");
        asm volatile("red.global.add.v4.f32 [%0], {%1,%2,%3,%4};"
                     :: "l"(sa), "f"(-h.x), "f"(-h.y), "f"(-h.z), "f"(-h.w) : "memory");

        e = en; s = sn; t = tn; wv = wvn; p1 = p1n; p2 = p2n;
    }
}

// ---------------------------------------------------------------------------
// K3 (exact round-7 form — the STG.64 remap regressed, reverted):
// out[b,n,:] = sigmoid(agg[b,n,:16] @ W_n[16,64] + b_n). Warp per node;
// lane owns cols {lane, lane+32}; packed fma2; MUFU sigmoid.
// ---------------------------------------------------------------------------
__global__ __launch_bounds__(256) void k3_nodes(
    const float* __restrict__ W_n, const float* __restrict__ b_n,
    float* __restrict__ out) {
    const int lane = threadIdx.x & 31;

    unsigned long long wA2[8], wB2[8];
#pragma unroll
    for (int j = 0; j < 8; j++) {
        wA2[j] = pack2(__ldg(W_n + (2 * j) * NO + lane),
                       __ldg(W_n + (2 * j + 1) * NO + lane));
        wB2[j] = pack2(__ldg(W_n + (2 * j) * NO + lane + 32),
                       __ldg(W_n + (2 * j + 1) * NO + lane + 32));
    }
    const float bA = __ldg(b_n + lane);
    const float bB = __ldg(b_n + lane + 32);

    const int tid    = blockIdx.x * blockDim.x + threadIdx.x;
    const int warpId = tid >> 5;
    const int nwarps = (gridDim.x * blockDim.x) >> 5;

    for (int node = warpId; node < Bb * Nn; node += nwarps) {
        const float* ag = g_agg + (size_t)node * 16;
        unsigned long long a[8];
#pragma unroll
        for (int j = 0; j < 4; j++)
            asm volatile("ld.global.nc.v2.b64 {%0, %1}, [%2];"
                         : "=l"(a[2 * j]), "=l"(a[2 * j + 1])
                         : "l"(ag + 4 * j));

        unsigned long long accA = 0ull, accB = 0ull;
#pragma unroll
        for (int j = 0; j < 8; j++) {
            accA = fma2(a[j], wA2[j], accA);
            accB = fma2(a[j], wB2[j], accB);
        }
        float2 sA = unpack2(accA), sB = unpack2(accB);
        out[(size_t)node * NO + lane]      = sigmoid_mufu(bA + sA.x + sA.y);
        out[(size_t)node * NO + lane + 32] = sigmoid_mufu(bB + sB.x + sB.y);
    }
}

// ---------------------------------------------------------------------------
// Launch: fork/join overlap. k2(b0) runs on a non-blocking side stream
// concurrently with k1(b1) on the main stream. Streams/events created once
// on the first (non-capture) correctness call; the captured graph contains
// the fork/join as dependency edges. Same work every call (deterministic).
// ---------------------------------------------------------------------------
static cudaStream_t g_s1 = nullptr;
static cudaEvent_t  g_e0 = nullptr, g_e1 = nullptr;

extern "C" void kernel_launch(void* const* d_in, const int* in_sizes, int n_in,
                              void* d_out, int out_size) {
    const float* x    = (const float*)d_in[0];
    const int*   esrc = (const int*)d_in[1];
    const int*   etgt = (const int*)d_in[2];
    const float* ew   = (const float*)d_in[3];
    const float* W_e  = (const float*)d_in[4];
    const float* b_e  = (const float*)d_in[5];
    const float* W_n  = (const float*)d_in[6];
    const float* b_n  = (const float*)d_in[7];
    float* out = (float*)d_out;

    if (!g_s1) {
        cudaStreamCreateWithFlags(&g_s1, cudaStreamNonBlocking);
        cudaEventCreateWithFlags(&g_e0, cudaEventDisableTiming);
        cudaEventCreateWithFlags(&g_e1, cudaEventDisableTiming);
    }

    // main: zero agg + P(batch0)
    k1_half<<<148 * 8, 128>>>(x, W_e, 0);
    cudaEventRecord(g_e0, 0);

    // side stream: edges(batch0), concurrent with P(batch1) below
    cudaStreamWaitEvent(g_s1, g_e0, 0);
    k2_edges<<<148 * 8, 256, 0, g_s1>>>(esrc, etgt, ew, W_e, b_e, 0);
    cudaEventRecord(g_e1, g_s1);

    // main: P(batch1), then edges(batch1)
    k1_half<<<148 * 8, 128>>>(x, W_e, 1);
    k2_edges<<<148 * 8, 256>>>(esrc, etgt, ew, W_e, b_e, 1);

    // join side stream, then node MLP
    cudaStreamWaitEvent(0, g_e1, 0);
    k3_nodes<<<148 * 8, 256>>>(W_n, b_n, out);
}

// round 16
// speedup vs baseline: 1.1055x; 1.0688x over previous
#include <cuda_runtime.h>
#include <cstdint>

// Problem constants
#define Bb 2
#define Nn 100000
#define Ff 64
#define Ee 800000
#define EO 16
#define NO 64

// Scratch (device globals — no allocation allowed)
__device__ float g_P[Bb * Nn * 32];    // [b][n][0:16]=x·W1, [16:32]=x·W2
__device__ float g_agg[Bb * Nn * 16];  // aggregation buffer

// ---------------------------------------------------------------------------
// Packed fp32x2 helpers (Blackwell sm_100+)
// ---------------------------------------------------------------------------
__device__ __forceinline__ unsigned long long pack2(float a, float b) {
    unsigned long long r;
    asm("mov.b64 %0, {%1, %2};" : "=l"(r) : "f"(a), "f"(b));
    return r;
}
__device__ __forceinline__ float2 unpack2(unsigned long long v) {
    float2 r;
    asm("mov.b64 {%0, %1}, %2;" : "=f"(r.x), "=f"(r.y) : "l"(v));
    return r;
}
__device__ __forceinline__ unsigned long long fma2(unsigned long long a,
                                                   unsigned long long b,
                                                   unsigned long long c) {
    unsigned long long d;
    asm("fma.rn.f32x2 %0, %1, %2, %3;" : "=l"(d) : "l"(a), "l"(b), "l"(c));
    return d;
}

// ---------------------------------------------------------------------------
// MUFU sigmoid: 2 MUFU + 2 FMA-pipe ops; MUFU pipe otherwise idle.
// ---------------------------------------------------------------------------
__device__ __forceinline__ float sigmoid_mufu(float x) {
    float e, r;
    asm("ex2.approx.ftz.f32 %0, %1;" : "=f"(e) : "f"(x * -1.4426950408889634f));
    asm("rcp.approx.ftz.f32 %0, %1;" : "=f"(r) : "f"(1.0f + e));
    return r;
}

// ---------------------------------------------------------------------------
// K1 (exact round-7 form, 35.8us proven): zero g_agg, then P = x @ [W1|W2].
// Round-4 lane mapping + 2-deep LDG prefetch; warp covers 2 nodes/iter with
// 4 independent fma2 chains; double-buffered smem.
// ---------------------------------------------------------------------------
__global__ __launch_bounds__(128) void k1_precompute(
    const float* __restrict__ x, const float* __restrict__ W_e) {
    __shared__ float xs[4][2][128];   // [warp][buf][2 node rows]

    const int tid = blockIdx.x * blockDim.x + threadIdx.x;
    const int nth = gridDim.x * blockDim.x;

    // Zero the aggregation buffer (vectorized)
    const float4 z4 = make_float4(0.f, 0.f, 0.f, 0.f);
    for (int i = tid; i < (Bb * Nn * 16) / 4; i += nth)
        ((float4*)g_agg)[i] = z4;

    const int lane  = threadIdx.x & 31;
    const int winb  = threadIdx.x >> 5;
    const int col   = lane & 15;
    const int rbase = (lane >= 16) ? 64 : 0;    // lanes 16..31 -> W2 rows

    unsigned long long w2[32];
#pragma unroll
    for (int k = 0; k < 32; k++)
        w2[k] = pack2(__ldg(W_e + (rbase + 2 * k) * EO + col),
                      __ldg(W_e + (rbase + 2 * k + 1) * EO + col));

    const uint32_t sb0 = (uint32_t)__cvta_generic_to_shared(&xs[winb][0][0]);
    const uint32_t sb1 = (uint32_t)__cvta_generic_to_shared(&xs[winb][1][0]);

    const int NP     = (Bb * Nn) / 2;
    const int warpId = tid >> 5;
    const int nwarps = nth >> 5;

    // 2-deep prefetch pipeline (tail prefetches clamp; values never used).
    float4 xv0 = ((const float4*)(x + (size_t)warpId * 128))[lane];
    {
        const int pr1 = warpId + nwarps;
        const int c1  = pr1 < NP ? pr1 : NP - 1;
        float4 xv1 = ((const float4*)(x + (size_t)c1 * 128))[lane];

        int p = 0;
        for (int pair = warpId; pair < NP; pair += nwarps) {
            ((float4*)(p ? xs[winb][1] : xs[winb][0]))[lane] = xv0;
            __syncwarp();
            xv0 = xv1;
            const int pr2 = pair + 2 * nwarps;
            const int c2  = pr2 < NP ? pr2 : NP - 1;
            xv1 = ((const float4*)(x + (size_t)c2 * 128))[lane];  // 2 ahead

            const uint32_t sb = p ? sb1 : sb0;
            unsigned long long accA0 = 0ull, accB0 = 0ull;
            unsigned long long accA1 = 0ull, accB1 = 0ull;
#pragma unroll
            for (int kk = 0; kk < 16; kk++) {
                unsigned long long a0, a1, b0, b1;
                asm volatile("ld.shared.v2.b64 {%0, %1}, [%2];"
                             : "=l"(a0), "=l"(a1) : "r"(sb + kk * 16));
                asm volatile("ld.shared.v2.b64 {%0, %1}, [%2];"
                             : "=l"(b0), "=l"(b1) : "r"(sb + 256 + kk * 16));
                accA0 = fma2(a0, w2[2 * kk],     accA0);
                accB0 = fma2(a1, w2[2 * kk + 1], accB0);
                accA1 = fma2(b0, w2[2 * kk],     accA1);
                accB1 = fma2(b1, w2[2 * kk + 1], accB1);
            }

            const float2 sA0 = unpack2(accA0), sB0 = unpack2(accB0);
            const float2 sA1 = unpack2(accA1), sB1 = unpack2(accB1);
            g_P[(size_t)pair * 64 + lane]      = (sA0.x + sA0.y) + (sB0.x + sB0.y);
            g_P[(size_t)pair * 64 + 32 + lane] = (sA1.x + sA1.y) + (sB1.x + sB1.y);
            p ^= 1;
        }
    }
}

// ---------------------------------------------------------------------------
// K2 (exact round-7 form — at the REDG lane-commit floor, ~31us/batch):
// 4 threads/edge-instance + 1-deep software prefetch of next indices +
// P gathers before current REDs. Internal batch loop (single launch).
// ---------------------------------------------------------------------------
__global__ __launch_bounds__(256) void k2_edges(
    const int* __restrict__ esrc, const int* __restrict__ etgt,
    const float* __restrict__ ew, const float* __restrict__ W_e,
    const float* __restrict__ b_e) {
    const int tid0 = blockIdx.x * blockDim.x + threadIdx.x;
    const int nth  = gridDim.x * blockDim.x;   // multiple of 4 -> q invariant
    const int q    = tid0 & 3;

    const float4 w3 = ((const float4*)(W_e + 128 * EO))[q];  // ew row
    const float4 bq = ((const float4*)b_e)[q];

#pragma unroll 1
    for (int b = 0; b < Bb; b++) {
        const float* Pb = g_P + (size_t)b * Nn * 32;
        float* aggb     = g_agg + (size_t)b * Nn * 16;

        // Prologue: stage iteration 0.
        int   e  = tid0 >> 2;
        int   s  = __ldg(esrc + e);
        int   t  = __ldg(etgt + e);
        float wv = __ldg(ew + e);
        float4 p1 = __ldg((const float4*)(Pb + (size_t)s * 32 + q * 4));
        float4 p2 = __ldg((const float4*)(Pb + (size_t)t * 32 + 16 + q * 4));

        for (int gid = tid0; gid < Ee * 4; gid += nth) {
            // Prefetch next iteration (clamped at the tail; values unused).
            const int gidn = gid + nth;
            const int en   = (gidn < Ee * 4) ? (gidn >> 2) : e;
            const int   sn  = __ldg(esrc + en);
            const int   tn  = __ldg(etgt + en);
            const float wvn = __ldg(ew + en);
            const float4 p1n = __ldg((const float4*)(Pb + (size_t)sn * 32 + q * 4));
            const float4 p2n = __ldg((const float4*)(Pb + (size_t)tn * 32 + 16 + q * 4));

            float4 h;
            h.x = sigmoid_mufu(fmaf(wv, w3.x, p1.x + p2.x + bq.x));
            h.y = sigmoid_mufu(fmaf(wv, w3.y, p1.y + p2.y + bq.y));
            h.z = sigmoid_mufu(fmaf(wv, w3.z, p1.z + p2.z + bq.z));
            h.w = sigmoid_mufu(fmaf(wv, w3.w, p1.w + p2.w + bq.w));

            float* ta = aggb + (size_t)t * 16 + q * 4;
            float* sa = aggb + (size_t)s * 16 + q * 4;
            asm volatile("red.global.add.v4.f32 [%0], {%1,%2,%3,%4};"
                         :: "l"(ta), "f"(h.x), "f"(h.y), "f"(h.z), "f"(h.w) : "memory");
            asm volatile("red.global.add.v4.f32 [%0], {%1,%2,%3,%4};"
                         :: "l"(sa), "f"(-h.x), "f"(-h.y), "f"(-h.z), "f"(-h.w) : "memory");

            e = en; s = sn; t = tn; wv = wvn; p1 = p1n; p2 = p2n;
        }
    }
}

// ---------------------------------------------------------------------------
// K3 NEW: half-warp per node. Lanes 0-15 own node0 (pair*2), lanes 16-31
// own node1; lane owns 4 ADJACENT cols [4*(lane&15), +4). Per 2 nodes:
// ONE STG.128 warp-op (512B fully coalesced; issue 12cyc vs 2x2 STG.32 =
// 20cyc) and 4 broadcast agg loads instead of 8. Same 512 fma2/node.
// ---------------------------------------------------------------------------
__global__ __launch_bounds__(256) void k3_nodes(
    const float* __restrict__ W_n, const float* __restrict__ b_n,
    float* __restrict__ out) {
    const int lane = threadIdx.x & 31;
    const int half = lane >> 4;          // which node of the pair
    const int cl   = lane & 15;
    const int c0   = 4 * cl;             // owned cols c0..c0+3

    // wc[c][j] = {W_n[2j][c0+c], W_n[2j+1][c0+c]}
    unsigned long long wc[4][8];
#pragma unroll
    for (int c = 0; c < 4; c++)
#pragma unroll
        for (int j = 0; j < 8; j++)
            wc[c][j] = pack2(__ldg(W_n + (2 * j) * NO + c0 + c),
                             __ldg(W_n + (2 * j + 1) * NO + c0 + c));
    float bb[4];
#pragma unroll
    for (int c = 0; c < 4; c++) bb[c] = __ldg(b_n + c0 + c);

    const int tid    = blockIdx.x * blockDim.x + threadIdx.x;
    const int warpId = tid >> 5;
    const int nwarps = (gridDim.x * blockDim.x) >> 5;
    const int NPAIR  = (Bb * Nn) / 2;

    for (int pair = warpId; pair < NPAIR; pair += nwarps) {
        const int node = pair * 2 + half;
        const float* ag = g_agg + (size_t)node * 16;
        unsigned long long a[8];
#pragma unroll
        for (int j = 0; j < 4; j++)   // broadcast within each half-warp
            asm volatile("ld.global.nc.v2.b64 {%0, %1}, [%2];"
                         : "=l"(a[2 * j]), "=l"(a[2 * j + 1])
                         : "l"(ag + 4 * j));

        unsigned long long acc[4] = {0ull, 0ull, 0ull, 0ull};
#pragma unroll
        for (int j = 0; j < 8; j++) {
            acc[0] = fma2(a[j], wc[0][j], acc[0]);
            acc[1] = fma2(a[j], wc[1][j], acc[1]);
            acc[2] = fma2(a[j], wc[2][j], acc[2]);
            acc[3] = fma2(a[j], wc[3][j], acc[3]);
        }

        float4 o;
        {
            const float2 s0 = unpack2(acc[0]);
            const float2 s1 = unpack2(acc[1]);
            const float2 s2 = unpack2(acc[2]);
            const float2 s3 = unpack2(acc[3]);
            o.x = sigmoid_mufu(bb[0] + s0.x + s0.y);
            o.y = sigmoid_mufu(bb[1] + s1.x + s1.y);
            o.z = sigmoid_mufu(bb[2] + s2.x + s2.y);
            o.w = sigmoid_mufu(bb[3] + s3.x + s3.y);
        }
        *(float4*)(out + (size_t)node * NO + c0) = o;   // one STG.128/warp pair
    }
}

// ---------------------------------------------------------------------------
extern "C" void kernel_launch(void* const* d_in, const int* in_sizes, int n_in,
                              void* d_out, int out_size) {
    const float* x    = (const float*)d_in[0];
    const int*   esrc = (const int*)d_in[1];
    const int*   etgt = (const int*)d_in[2];
    const float* ew   = (const float*)d_in[3];
    const float* W_e  = (const float*)d_in[4];
    const float* b_e  = (const float*)d_in[5];
    const float* W_n  = (const float*)d_in[6];
    const float* b_n  = (const float*)d_in[7];
    float* out = (float*)d_out;

    k1_precompute<<<148 * 16, 128>>>(x, W_e);
    k2_edges<<<148 * 8, 256>>>(esrc, etgt, ew, W_e, b_e);
    k3_nodes<<<148 * 8, 256>>>(W_n, b_n, out);
}

// round 17
// speedup vs baseline: 1.2118x; 1.0962x over previous
#include <cuda_runtime.h>
#include <cstdint>

// Problem constants
#define Bb 2
#define Nn 100000
#define Ff 64
#define Ee 800000
#define EO 16
#define NO 64

// Scratch (device globals — no allocation allowed)
__device__ float g_P[Bb * Nn * 32];    // [b][n][0:16]=x·W1, [16:32]=x·W2
__device__ float g_agg[Bb * Nn * 16];  // aggregation buffer

// ---------------------------------------------------------------------------
// Packed fp32x2 helpers (Blackwell sm_100+)
// ---------------------------------------------------------------------------
__device__ __forceinline__ unsigned long long pack2(float a, float b) {
    unsigned long long r;
    asm("mov.b64 %0, {%1, %2};" : "=l"(r) : "f"(a), "f"(b));
    return r;
}
__device__ __forceinline__ float2 unpack2(unsigned long long v) {
    float2 r;
    asm("mov.b64 {%0, %1}, %2;" : "=f"(r.x), "=f"(r.y) : "l"(v));
    return r;
}
__device__ __forceinline__ unsigned long long fma2(unsigned long long a,
                                                   unsigned long long b,
                                                   unsigned long long c) {
    unsigned long long d;
    asm("fma.rn.f32x2 %0, %1, %2, %3;" : "=l"(d) : "l"(a), "l"(b), "l"(c));
    return d;
}

// ---------------------------------------------------------------------------
// MUFU sigmoid: 2 MUFU + 2 FMA-pipe ops; MUFU pipe otherwise idle.
// ---------------------------------------------------------------------------
__device__ __forceinline__ float sigmoid_mufu(float x) {
    float e, r;
    asm("ex2.approx.ftz.f32 %0, %1;" : "=f"(e) : "f"(x * -1.4426950408889634f));
    asm("rcp.approx.ftz.f32 %0, %1;" : "=f"(r) : "f"(1.0f + e));
    return r;
}

// ---------------------------------------------------------------------------
// K1 (exact round-7 form, 35.8us proven): zero g_agg, then P = x @ [W1|W2].
// Round-4 lane mapping + 2-deep LDG prefetch; warp covers 2 nodes/iter with
// 4 independent fma2 chains; double-buffered smem. Grid 2368 = exactly 4
// waves at 4 CTAs/SM — already wave-aligned.
// ---------------------------------------------------------------------------
__global__ __launch_bounds__(128) void k1_precompute(
    const float* __restrict__ x, const float* __restrict__ W_e) {
    __shared__ float xs[4][2][128];   // [warp][buf][2 node rows]

    const int tid = blockIdx.x * blockDim.x + threadIdx.x;
    const int nth = gridDim.x * blockDim.x;

    // Zero the aggregation buffer (vectorized)
    const float4 z4 = make_float4(0.f, 0.f, 0.f, 0.f);
    for (int i = tid; i < (Bb * Nn * 16) / 4; i += nth)
        ((float4*)g_agg)[i] = z4;

    const int lane  = threadIdx.x & 31;
    const int winb  = threadIdx.x >> 5;
    const int col   = lane & 15;
    const int rbase = (lane >= 16) ? 64 : 0;    // lanes 16..31 -> W2 rows

    unsigned long long w2[32];
#pragma unroll
    for (int k = 0; k < 32; k++)
        w2[k] = pack2(__ldg(W_e + (rbase + 2 * k) * EO + col),
                      __ldg(W_e + (rbase + 2 * k + 1) * EO + col));

    const uint32_t sb0 = (uint32_t)__cvta_generic_to_shared(&xs[winb][0][0]);
    const uint32_t sb1 = (uint32_t)__cvta_generic_to_shared(&xs[winb][1][0]);

    const int NP     = (Bb * Nn) / 2;
    const int warpId = tid >> 5;
    const int nwarps = nth >> 5;

    // 2-deep prefetch pipeline (tail prefetches clamp; values never used).
    float4 xv0 = ((const float4*)(x + (size_t)warpId * 128))[lane];
    {
        const int pr1 = warpId + nwarps;
        const int c1  = pr1 < NP ? pr1 : NP - 1;
        float4 xv1 = ((const float4*)(x + (size_t)c1 * 128))[lane];

        int p = 0;
        for (int pair = warpId; pair < NP; pair += nwarps) {
            ((float4*)(p ? xs[winb][1] : xs[winb][0]))[lane] = xv0;
            __syncwarp();
            xv0 = xv1;
            const int pr2 = pair + 2 * nwarps;
            const int c2  = pr2 < NP ? pr2 : NP - 1;
            xv1 = ((const float4*)(x + (size_t)c2 * 128))[lane];  // 2 ahead

            const uint32_t sb = p ? sb1 : sb0;
            unsigned long long accA0 = 0ull, accB0 = 0ull;
            unsigned long long accA1 = 0ull, accB1 = 0ull;
#pragma unroll
            for (int kk = 0; kk < 16; kk++) {
                unsigned long long a0, a1, b0, b1;
                asm volatile("ld.shared.v2.b64 {%0, %1}, [%2];"
                             : "=l"(a0), "=l"(a1) : "r"(sb + kk * 16));
                asm volatile("ld.shared.v2.b64 {%0, %1}, [%2];"
                             : "=l"(b0), "=l"(b1) : "r"(sb + 256 + kk * 16));
                accA0 = fma2(a0, w2[2 * kk],     accA0);
                accB0 = fma2(a1, w2[2 * kk + 1], accB0);
                accA1 = fma2(b0, w2[2 * kk],     accA1);
                accB1 = fma2(b1, w2[2 * kk + 1], accB1);
            }

            const float2 sA0 = unpack2(accA0), sB0 = unpack2(accB0);
            const float2 sA1 = unpack2(accA1), sB1 = unpack2(accB1);
            g_P[(size_t)pair * 64 + lane]      = (sA0.x + sA0.y) + (sB0.x + sB0.y);
            g_P[(size_t)pair * 64 + 32 + lane] = (sA1.x + sA1.y) + (sB1.x + sB1.y);
            p ^= 1;
        }
    }
}

// ---------------------------------------------------------------------------
// K2 (round-7 body; grid fixed to ONE resident wave): at 40 regs x 256 thr
// only 6 CTAs fit per SM, so grid 148*8 ran 1.33 ragged waves. 148*6 = 888
// CTAs = exactly one persistent wave; grid-stride absorbs the work evenly.
// ---------------------------------------------------------------------------
__global__ __launch_bounds__(256) void k2_edges(
    const int* __restrict__ esrc, const int* __restrict__ etgt,
    const float* __restrict__ ew, const float* __restrict__ W_e,
    const float* __restrict__ b_e) {
    const int tid0 = blockIdx.x * blockDim.x + threadIdx.x;
    const int nth  = gridDim.x * blockDim.x;   // multiple of 4 -> q invariant
    const int q    = tid0 & 3;

    const float4 w3 = ((const float4*)(W_e + 128 * EO))[q];  // ew row
    const float4 bq = ((const float4*)b_e)[q];

#pragma unroll 1
    for (int b = 0; b < Bb; b++) {
        const float* Pb = g_P + (size_t)b * Nn * 32;
        float* aggb     = g_agg + (size_t)b * Nn * 16;

        // Prologue: stage iteration 0.
        int   e  = tid0 >> 2;
        int   s  = __ldg(esrc + e);
        int   t  = __ldg(etgt + e);
        float wv = __ldg(ew + e);
        float4 p1 = __ldg((const float4*)(Pb + (size_t)s * 32 + q * 4));
        float4 p2 = __ldg((const float4*)(Pb + (size_t)t * 32 + 16 + q * 4));

        for (int gid = tid0; gid < Ee * 4; gid += nth) {
            // Prefetch next iteration (clamped at the tail; values unused).
            const int gidn = gid + nth;
            const int en   = (gidn < Ee * 4) ? (gidn >> 2) : e;
            const int   sn  = __ldg(esrc + en);
            const int   tn  = __ldg(etgt + en);
            const float wvn = __ldg(ew + en);
            const float4 p1n = __ldg((const float4*)(Pb + (size_t)sn * 32 + q * 4));
            const float4 p2n = __ldg((const float4*)(Pb + (size_t)tn * 32 + 16 + q * 4));

            float4 h;
            h.x = sigmoid_mufu(fmaf(wv, w3.x, p1.x + p2.x + bq.x));
            h.y = sigmoid_mufu(fmaf(wv, w3.y, p1.y + p2.y + bq.y));
            h.z = sigmoid_mufu(fmaf(wv, w3.z, p1.z + p2.z + bq.z));
            h.w = sigmoid_mufu(fmaf(wv, w3.w, p1.w + p2.w + bq.w));

            float* ta = aggb + (size_t)t * 16 + q * 4;
            float* sa = aggb + (size_t)s * 16 + q * 4;
            asm volatile("red.global.add.v4.f32 [%0], {%1,%2,%3,%4};"
                         :: "l"(ta), "f"(h.x), "f"(h.y), "f"(h.z), "f"(h.w) : "memory");
            asm volatile("red.global.add.v4.f32 [%0], {%1,%2,%3,%4};"
                         :: "l"(sa), "f"(-h.x), "f"(-h.y), "f"(-h.z), "f"(-h.w) : "memory");

            e = en; s = sn; t = tn; wv = wvn; p1 = p1n; p2 = p2n;
        }
    }
}

// ---------------------------------------------------------------------------
// K3 (round-16 winning form; grid fixed to one resident wave at ~2 CTAs/SM):
// half-warp per node, lane owns 4 adjacent cols, one STG.128 per node pair.
// ---------------------------------------------------------------------------
__global__ __launch_bounds__(256) void k3_nodes(
    const float* __restrict__ W_n, const float* __restrict__ b_n,
    float* __restrict__ out) {
    const int lane = threadIdx.x & 31;
    const int half = lane >> 4;          // which node of the pair
    const int cl   = lane & 15;
    const int c0   = 4 * cl;             // owned cols c0..c0+3

    // wc[c][j] = {W_n[2j][c0+c], W_n[2j+1][c0+c]}
    unsigned long long wc[4][8];
#pragma unroll
    for (int c = 0; c < 4; c++)
#pragma unroll
        for (int j = 0; j < 8; j++)
            wc[c][j] = pack2(__ldg(W_n + (2 * j) * NO + c0 + c),
                             __ldg(W_n + (2 * j + 1) * NO + c0 + c));
    float bb[4];
#pragma unroll
    for (int c = 0; c < 4; c++) bb[c] = __ldg(b_n + c0 + c);

    const int tid    = blockIdx.x * blockDim.x + threadIdx.x;
    const int warpId = tid >> 5;
    const int nwarps = (gridDim.x * blockDim.x) >> 5;
    const int NPAIR  = (Bb * Nn) / 2;

    for (int pair = warpId; pair < NPAIR; pair += nwarps) {
        const int node = pair * 2 + half;
        const float* ag = g_agg + (size_t)node * 16;
        unsigned long long a[8];
#pragma unroll
        for (int j = 0; j < 4; j++)   // broadcast within each half-warp
            asm volatile("ld.global.nc.v2.b64 {%0, %1}, [%2];"
                         : "=l"(a[2 * j]), "=l"(a[2 * j + 1])
                         : "l"(ag + 4 * j));

        unsigned long long acc[4] = {0ull, 0ull, 0ull, 0ull};
#pragma unroll
        for (int j = 0; j < 8; j++) {
            acc[0] = fma2(a[j], wc[0][j], acc[0]);
            acc[1] = fma2(a[j], wc[1][j], acc[1]);
            acc[2] = fma2(a[j], wc[2][j], acc[2]);
            acc[3] = fma2(a[j], wc[3][j], acc[3]);
        }

        float4 o;
        {
            const float2 s0 = unpack2(acc[0]);
            const float2 s1 = unpack2(acc[1]);
            const float2 s2 = unpack2(acc[2]);
            const float2 s3 = unpack2(acc[3]);
            o.x = sigmoid_mufu(bb[0] + s0.x + s0.y);
            o.y = sigmoid_mufu(bb[1] + s1.x + s1.y);
            o.z = sigmoid_mufu(bb[2] + s2.x + s2.y);
            o.w = sigmoid_mufu(bb[3] + s3.x + s3.y);
        }
        *(float4*)(out + (size_t)node * NO + c0) = o;   // one STG.128/warp pair
    }
}

// ---------------------------------------------------------------------------
extern "C" void kernel_launch(void* const* d_in, const int* in_sizes, int n_in,
                              void* d_out, int out_size) {
    const float* x    = (const float*)d_in[0];
    const int*   esrc = (const int*)d_in[1];
    const int*   etgt = (const int*)d_in[2];
    const float* ew   = (const float*)d_in[3];
    const float* W_e  = (const float*)d_in[4];
    const float* b_e  = (const float*)d_in[5];
    const float* W_n  = (const float*)d_in[6];
    const float* b_n  = (const float*)d_in[7];
    float* out = (float*)d_out;

    k1_precompute<<<148 * 16, 128>>>(x, W_e);
    k2_edges<<<148 * 6, 256>>>(esrc, etgt, ew, W_e, b_e);   // 1 resident wave
    k3_nodes<<<148 * 2, 256>>>(W_n, b_n, out);              // 1 resident wave
}